// round 1
// baseline (speedup 1.0000x reference)
#include <cuda_runtime.h>
#include <math.h>

#define NB 256
#define S 1
#define IH 144
#define IW 256
#define HR 144
#define WR 256
#define F 16
#define D 128

#define FOV_HALF 0.654498469497874f   // 0.5 * 75deg in rad
#define GELU_GAMMA 1.7015043497085571f

// Scratch (no allocations allowed)
__device__ float4 g_dir[HR * WR];      // (dx, dy, dz, 0) per retina pixel
__device__ float  g_rm[NB * 9];        // rotation matrices

// ---------------------------------------------------------------------------
// Kernel 1: per-pixel retina ray directions (batch-invariant)
// ---------------------------------------------------------------------------
__global__ void dir_kernel() {
    int w = threadIdx.x;
    int h = blockIdx.x;
    float gx = ((float)(2 * w + 1 - WR)) * (1.0f / 256.0f);
    float gy = ((float)(2 * h + 1 - HR)) * (1.0f / 256.0f);
    float ax = gx * FOV_HALF;
    float ay = gy * FOV_HALF;
    float a = sqrtf(ax * ax + ay * ay) + 1e-12f;
    float s, c;
    sincosf(a, &s, &c);
    float sinc = s / a;
    g_dir[h * WR + w] = make_float4(sinc * ax, sinc * ay, c, 0.0f);
}

// ---------------------------------------------------------------------------
// Kernel 2: per-batch MLP -> Euler angles -> rotation matrix
// one block per batch, 128 threads
// ---------------------------------------------------------------------------
__device__ __forceinline__ float gelu_tanh(float x) {
    // matches jax.nn.gelu(approximate=True)
    float x3 = x * x * x;
    float inner = 0.7978845608028654f * (x + 0.044715f * x3);
    float t = tanhf(inner);
    return 0.5f * x * (1.0f + t);
}

__global__ void mlp_kernel(const float* __restrict__ persp,
                           const float* __restrict__ W1, const float* __restrict__ b1,
                           const float* __restrict__ W2, const float* __restrict__ b2,
                           const float* __restrict__ Wp, const float* __restrict__ bp) {
    __shared__ float sp[F];
    __shared__ float h1[D];
    __shared__ float h2[D];
    __shared__ float sang[3];

    int n = blockIdx.x;
    int tid = threadIdx.x;

    if (tid < F) sp[tid] = persp[n * F + tid];
    __syncthreads();

    // layer 1: [16] @ [16,128]
    float acc = b1[tid];
#pragma unroll
    for (int k = 0; k < F; k++)
        acc = fmaf(sp[k], __ldg(&W1[k * D + tid]), acc);
    h1[tid] = gelu_tanh(acc) * GELU_GAMMA;
    __syncthreads();

    // layer 2: [128] @ [128,128]
    float acc2 = b2[tid];
#pragma unroll 8
    for (int k = 0; k < D; k++)
        acc2 = fmaf(h1[k], __ldg(&W2[k * D + tid]), acc2);
    h2[tid] = gelu_tanh(acc2) * GELU_GAMMA;
    __syncthreads();

    // projection to 3 angles
    if (tid < 3) {
        float a = bp[tid];
        for (int k = 0; k < D; k++)
            a = fmaf(h2[k], __ldg(&Wp[k * 3 + tid]), a);
        sang[tid] = a;
    }
    __syncthreads();

    if (tid == 0) {
        float axr = sang[0], ayr = sang[1], azr = sang[2];
        float cx, sx, cy, sy, cz, sz;
        sincosf(axr, &sx, &cx);
        sincosf(ayr, &sy, &cy);
        sincosf(azr, &sz, &cz);
        // R = Rz @ Ry @ Rx
        float* r = &g_rm[n * 9];
        r[0] = cz * cy;
        r[1] = cz * sy * sx - sz * cx;
        r[2] = cz * sy * cx + sz * sx;
        r[3] = sz * cy;
        r[4] = sz * sy * sx + cz * cx;
        r[5] = sz * sy * cx - cz * sx;
        r[6] = -sy;
        r[7] = cy * sx;
        r[8] = cy * cx;
    }
}

// ---------------------------------------------------------------------------
// Kernel 3: rotate rays, project, bilinear sample
// block = 256 threads (one row), grid = (HR, NB)
// ---------------------------------------------------------------------------
__global__ void sample_kernel(const float* __restrict__ stim,
                              float* __restrict__ out) {
    __shared__ float r[9];
    int w = threadIdx.x;
    int h = blockIdx.x;
    int n = blockIdx.y;

    if (threadIdx.x < 9) r[threadIdx.x] = g_rm[n * 9 + threadIdx.x];
    __syncthreads();

    float4 d = g_dir[h * WR + w];

    float rx = r[0] * d.x + r[1] * d.y + r[2] * d.z;
    float ry = r[3] * d.x + r[4] * d.y + r[5] * d.z;
    float rz = r[6] * d.x + r[7] * d.y + r[8] * d.z;

    bool safe = rz > 0.001f;
    float inv = __fdividef(1.0f, rz);
    // px = gx*128 + 127.5 ; py = gy*128 + 71.5  (m = 256, W = 256, H = 144)
    float px = safe ? fmaf(rx * inv, 128.0f, 127.5f) : 1.0e8f;
    float py = safe ? fmaf(ry * inv, 128.0f, 71.5f) : 1.0e8f;

    float x0f = floorf(px);
    float y0f = floorf(py);
    float wx = px - x0f;
    float wy = py - y0f;
    int x0 = (int)x0f;
    int y0 = (int)y0f;
    int x1 = x0 + 1;
    int y1 = y0 + 1;

    bool vx0 = (unsigned)x0 < (unsigned)IW;
    bool vx1 = (unsigned)x1 < (unsigned)IW;
    bool vy0 = (unsigned)y0 < (unsigned)IH;
    bool vy1 = (unsigned)y1 < (unsigned)IH;

    int xc0 = min(max(x0, 0), IW - 1);
    int xc1 = min(max(x1, 0), IW - 1);
    int yc0 = min(max(y0, 0), IH - 1);
    int yc1 = min(max(y1, 0), IH - 1);

    const float* img = stim + (size_t)n * (IH * IW);
    int b0 = yc0 * IW;
    int b1r = yc1 * IW;

    float v00 = (vy0 && vx0) ? __ldg(img + b0 + xc0) : 0.0f;
    float v01 = (vy0 && vx1) ? __ldg(img + b0 + xc1) : 0.0f;
    float v10 = (vy1 && vx0) ? __ldg(img + b1r + xc0) : 0.0f;
    float v11 = (vy1 && vx1) ? __ldg(img + b1r + xc1) : 0.0f;

    float top = fmaf(wx, v01 - v00, v00);
    float bot = fmaf(wx, v11 - v10, v10);
    float val = fmaf(wy, bot - top, top);

    out[((size_t)n * IH + h) * IW + w] = val;
}

// ---------------------------------------------------------------------------
extern "C" void kernel_launch(void* const* d_in, const int* in_sizes, int n_in,
                              void* d_out, int out_size) {
    const float* stimulus = (const float*)d_in[0];
    const float* persp    = (const float*)d_in[1];
    const float* W1       = (const float*)d_in[2];
    const float* b1       = (const float*)d_in[3];
    const float* W2       = (const float*)d_in[4];
    const float* b2       = (const float*)d_in[5];
    const float* Wp       = (const float*)d_in[6];
    const float* bp       = (const float*)d_in[7];
    float* out = (float*)d_out;

    dir_kernel<<<HR, WR>>>();
    mlp_kernel<<<NB, D>>>(persp, W1, b1, W2, b2, Wp, bp);
    sample_kernel<<<dim3(HR, NB), WR>>>(stimulus, out);
}

// round 2
// speedup vs baseline: 1.2644x; 1.2644x over previous
#include <cuda_runtime.h>
#include <math.h>

#define NB 256
#define IH 144
#define IW 256
#define HR 144
#define WR 256
#define F 16
#define D 128
#define BPT 4   // batches per thread in sample kernel

#define FOV_HALF 0.654498469497874f   // 0.5 * 75deg in rad
#define GELU_GAMMA 1.7015043497085571f

// Scratch (no allocations allowed)
__device__ float4 g_dir[HR * WR];      // (dx, dy, dz, 0) per retina pixel
__device__ float  g_rm[NB * 9];        // rotation matrices

__device__ __forceinline__ float gelu_tanh(float x) {
    // matches jax.nn.gelu(approximate=True)
    float x3 = x * x * x;
    float inner = 0.7978845608028654f * (x + 0.044715f * x3);
    float t = tanhf(inner);
    return 0.5f * x * (1.0f + t);
}

// ---------------------------------------------------------------------------
// Kernel 1 (merged): blocks [0, HR) build the dir table; blocks [HR, HR+NB)
// run the per-batch MLP -> Euler angles -> rotation matrix.
// ---------------------------------------------------------------------------
__global__ void setup_kernel(const float* __restrict__ persp,
                             const float* __restrict__ W1, const float* __restrict__ b1,
                             const float* __restrict__ W2, const float* __restrict__ b2,
                             const float* __restrict__ Wp, const float* __restrict__ bp) {
    if (blockIdx.x < HR) {
        // ---- dir table ----
        int w = threadIdx.x;
        int h = blockIdx.x;
        float gx = ((float)(2 * w + 1 - WR)) * (1.0f / 256.0f);
        float gy = ((float)(2 * h + 1 - HR)) * (1.0f / 256.0f);
        float ax = gx * FOV_HALF;
        float ay = gy * FOV_HALF;
        float a = sqrtf(ax * ax + ay * ay) + 1e-12f;
        float s, c;
        sincosf(a, &s, &c);
        float sinc = s / a;
        g_dir[h * WR + w] = make_float4(sinc * ax, sinc * ay, c, 0.0f);
        return;
    }

    // ---- MLP ----
    __shared__ float sp[F];
    __shared__ float h1[D];
    __shared__ float h2[D];
    __shared__ float sang[3];

    int n = blockIdx.x - HR;
    int tid = threadIdx.x;

    if (tid < F) sp[tid] = persp[n * F + tid];
    __syncthreads();

    if (tid < D) {
        float acc = b1[tid];
#pragma unroll
        for (int k = 0; k < F; k++)
            acc = fmaf(sp[k], __ldg(&W1[k * D + tid]), acc);
        h1[tid] = gelu_tanh(acc) * GELU_GAMMA;
    }
    __syncthreads();

    if (tid < D) {
        float acc2 = b2[tid];
#pragma unroll 8
        for (int k = 0; k < D; k++)
            acc2 = fmaf(h1[k], __ldg(&W2[k * D + tid]), acc2);
        h2[tid] = gelu_tanh(acc2) * GELU_GAMMA;
    }
    __syncthreads();

    if (tid < 3) {
        float a = bp[tid];
        for (int k = 0; k < D; k++)
            a = fmaf(h2[k], __ldg(&Wp[k * 3 + tid]), a);
        sang[tid] = a;
    }
    __syncthreads();

    if (tid == 0) {
        float axr = sang[0], ayr = sang[1], azr = sang[2];
        float cx, sx, cy, sy, cz, sz;
        sincosf(axr, &sx, &cx);
        sincosf(ayr, &sy, &cy);
        sincosf(azr, &sz, &cz);
        // R = Rz @ Ry @ Rx
        float* r = &g_rm[n * 9];
        r[0] = cz * cy;
        r[1] = cz * sy * sx - sz * cx;
        r[2] = cz * sy * cx + sz * sx;
        r[3] = sz * cy;
        r[4] = sz * sy * sx + cz * cx;
        r[5] = sz * sy * cx - cz * sx;
        r[6] = -sy;
        r[7] = cy * sx;
        r[8] = cy * cx;
    }
}

// ---------------------------------------------------------------------------
// Kernel 2: rotate rays, project, bilinear sample. BPT batches per thread:
// the dir load (L2) is amortized across BPT batches, and the 4*BPT gathers
// give deep memory-level parallelism.
// grid = (HR, NB/BPT), block = WR
// ---------------------------------------------------------------------------
__global__ void __launch_bounds__(WR) sample_kernel(const float* __restrict__ stim,
                                                    float* __restrict__ out) {
    __shared__ float r[BPT * 9];
    int w = threadIdx.x;
    int h = blockIdx.x;
    int nb = blockIdx.y * BPT;

    if (threadIdx.x < BPT * 9) r[threadIdx.x] = g_rm[nb * 9 + threadIdx.x];
    __syncthreads();

    float4 d = g_dir[h * WR + w];

#pragma unroll
    for (int b = 0; b < BPT; b++) {
        const float* rb = &r[b * 9];
        float rx = rb[0] * d.x + rb[1] * d.y + rb[2] * d.z;
        float ry = rb[3] * d.x + rb[4] * d.y + rb[5] * d.z;
        float rz = rb[6] * d.x + rb[7] * d.y + rb[8] * d.z;

        bool safe = rz > 0.001f;
        float inv = __fdividef(1.0f, rz);
        // px = gx*128 + 127.5 ; py = gy*128 + 71.5  (m = 256, W = 256, H = 144)
        float px = safe ? fmaf(rx * inv, 128.0f, 127.5f) : 1.0e8f;
        float py = safe ? fmaf(ry * inv, 128.0f, 71.5f) : 1.0e8f;

        float x0f = floorf(px);
        float y0f = floorf(py);
        float wx = px - x0f;
        float wy = py - y0f;
        int x0 = (int)x0f;
        int y0 = (int)y0f;
        int x1 = x0 + 1;
        int y1 = y0 + 1;

        bool vx0 = (unsigned)x0 < (unsigned)IW;
        bool vx1 = (unsigned)x1 < (unsigned)IW;
        bool vy0 = (unsigned)y0 < (unsigned)IH;
        bool vy1 = (unsigned)y1 < (unsigned)IH;

        int xc0 = min(max(x0, 0), IW - 1);
        int xc1 = min(max(x1, 0), IW - 1);
        int yc0 = min(max(y0, 0), IH - 1);
        int yc1 = min(max(y1, 0), IH - 1);

        const float* img = stim + (size_t)(nb + b) * (IH * IW);
        int r0 = yc0 * IW;
        int r1 = yc1 * IW;

        float v00 = (vy0 && vx0) ? __ldg(img + r0 + xc0) : 0.0f;
        float v01 = (vy0 && vx1) ? __ldg(img + r0 + xc1) : 0.0f;
        float v10 = (vy1 && vx0) ? __ldg(img + r1 + xc0) : 0.0f;
        float v11 = (vy1 && vx1) ? __ldg(img + r1 + xc1) : 0.0f;

        float top = fmaf(wx, v01 - v00, v00);
        float bot = fmaf(wx, v11 - v10, v10);
        float val = fmaf(wy, bot - top, top);

        out[((size_t)(nb + b) * IH + h) * IW + w] = val;
    }
}

// ---------------------------------------------------------------------------
extern "C" void kernel_launch(void* const* d_in, const int* in_sizes, int n_in,
                              void* d_out, int out_size) {
    const float* stimulus = (const float*)d_in[0];
    const float* persp    = (const float*)d_in[1];
    const float* W1       = (const float*)d_in[2];
    const float* b1       = (const float*)d_in[3];
    const float* W2       = (const float*)d_in[4];
    const float* b2       = (const float*)d_in[5];
    const float* Wp       = (const float*)d_in[6];
    const float* bp       = (const float*)d_in[7];
    float* out = (float*)d_out;

    setup_kernel<<<HR + NB, WR>>>(persp, W1, b1, W2, b2, Wp, bp);
    sample_kernel<<<dim3(HR, NB / BPT), WR>>>(stimulus, out);
}

// round 3
// speedup vs baseline: 1.2821x; 1.0140x over previous
#include <cuda_runtime.h>
#include <math.h>

#define NB 256
#define IH 144
#define IW 256
#define HR 144
#define WR 256
#define F 16
#define D 128
#define BPT 4   // batches per block (sample kernel)
#define VPT 4   // x-pixels per thread (strided by 64)

#define FOV_HALF 0.654498469497874f   // 0.5 * 75deg in rad
#define GELU_GAMMA 1.7015043497085571f

// Scratch (no allocations allowed)
__device__ float4 g_dir[HR * WR];      // (dx, dy, dz, 0) per retina pixel
__device__ float  g_rm[NB * 9];        // rotation matrices

__device__ __forceinline__ float gelu_tanh(float x) {
    // matches jax.nn.gelu(approximate=True)
    float x3 = x * x * x;
    float inner = 0.7978845608028654f * (x + 0.044715f * x3);
    float t = tanhf(inner);
    return 0.5f * x * (1.0f + t);
}

// ---------------------------------------------------------------------------
// Kernel 1 (merged): blocks [0, HR) build the dir table; blocks [HR, HR+NB)
// run the per-batch MLP -> Euler angles -> rotation matrix.
// ---------------------------------------------------------------------------
__global__ void setup_kernel(const float* __restrict__ persp,
                             const float* __restrict__ W1, const float* __restrict__ b1,
                             const float* __restrict__ W2, const float* __restrict__ b2,
                             const float* __restrict__ Wp, const float* __restrict__ bp) {
    if (blockIdx.x < HR) {
        // ---- dir table ----
        int w = threadIdx.x;
        int h = blockIdx.x;
        float gx = ((float)(2 * w + 1 - WR)) * (1.0f / 256.0f);
        float gy = ((float)(2 * h + 1 - HR)) * (1.0f / 256.0f);
        float ax = gx * FOV_HALF;
        float ay = gy * FOV_HALF;
        float a = sqrtf(ax * ax + ay * ay) + 1e-12f;
        float s, c;
        sincosf(a, &s, &c);
        float sinc = s / a;
        g_dir[h * WR + w] = make_float4(sinc * ax, sinc * ay, c, 0.0f);
        return;
    }

    // ---- MLP ----
    __shared__ float sp[F];
    __shared__ float h1[D];
    __shared__ float h2[D];
    __shared__ float sang[3];

    int n = blockIdx.x - HR;
    int tid = threadIdx.x;

    if (tid < F) sp[tid] = persp[n * F + tid];
    __syncthreads();

    if (tid < D) {
        float acc = b1[tid];
#pragma unroll
        for (int k = 0; k < F; k++)
            acc = fmaf(sp[k], __ldg(&W1[k * D + tid]), acc);
        h1[tid] = gelu_tanh(acc) * GELU_GAMMA;
    }
    __syncthreads();

    if (tid < D) {
        float acc2 = b2[tid];
#pragma unroll 8
        for (int k = 0; k < D; k++)
            acc2 = fmaf(h1[k], __ldg(&W2[k * D + tid]), acc2);
        h2[tid] = gelu_tanh(acc2) * GELU_GAMMA;
    }
    __syncthreads();

    if (tid < 3) {
        float a = bp[tid];
        for (int k = 0; k < D; k++)
            a = fmaf(h2[k], __ldg(&Wp[k * 3 + tid]), a);
        sang[tid] = a;
    }
    __syncthreads();

    if (tid == 0) {
        float axr = sang[0], ayr = sang[1], azr = sang[2];
        float cx, sx, cy, sy, cz, sz;
        sincosf(axr, &sx, &cx);
        sincosf(ayr, &sy, &cy);
        sincosf(azr, &sz, &cz);
        // R = Rz @ Ry @ Rx
        float* r = &g_rm[n * 9];
        r[0] = cz * cy;
        r[1] = cz * sy * sx - sz * cx;
        r[2] = cz * sy * cx + sz * sx;
        r[3] = sz * cy;
        r[4] = sz * sy * sx + cz * cx;
        r[5] = sz * sy * cx - cz * sx;
        r[6] = -sy;
        r[7] = cy * sx;
        r[8] = cy * cx;
    }
}

// ---------------------------------------------------------------------------
// Kernel 2: rotate rays, project, bilinear sample.
//   block = 256 threads = 4 rows x 64 lanes; each thread handles VPT=4
//   x-pixels strided by 64 (coalesced dir loads + tight gathers), and the
//   batch loop (BPT=4) keeps the 9 rotation coefficients in registers.
//   grid = (HR/4, NB/BPT)
// ---------------------------------------------------------------------------
__global__ void __launch_bounds__(256) sample_kernel(const float* __restrict__ stim,
                                                     float* __restrict__ out) {
    int tx = threadIdx.x;
    int lane = tx & 63;        // x base 0..63
    int row = tx >> 6;         // 0..3
    int h = blockIdx.x * 4 + row;
    int nb = blockIdx.y * BPT;

    // direction vectors for this thread's 4 pixels (x = lane + 64*j)
    float dx[VPT], dy[VPT], dz[VPT];
#pragma unroll
    for (int j = 0; j < VPT; j++) {
        float4 d = g_dir[h * WR + lane + 64 * j];
        dx[j] = d.x; dy[j] = d.y; dz[j] = d.z;
    }

    const float* rmp = &g_rm[nb * 9];
    const float* img = stim + (size_t)nb * (IH * IW);
    float* outp = out + ((size_t)nb * IH + h) * IW + lane;

#pragma unroll 1
    for (int b = 0; b < BPT; b++) {
        // rotation matrix in registers (broadcast loads)
        float r0 = __ldg(rmp + 0), r1 = __ldg(rmp + 1), r2 = __ldg(rmp + 2);
        float r3 = __ldg(rmp + 3), r4 = __ldg(rmp + 4), r5 = __ldg(rmp + 5);
        float r6 = __ldg(rmp + 6), r7 = __ldg(rmp + 7), r8 = __ldg(rmp + 8);

#pragma unroll
        for (int j = 0; j < VPT; j++) {
            float rx = fmaf(r0, dx[j], fmaf(r1, dy[j], r2 * dz[j]));
            float ry = fmaf(r3, dx[j], fmaf(r4, dy[j], r5 * dz[j]));
            float rz = fmaf(r6, dx[j], fmaf(r7, dy[j], r8 * dz[j]));

            bool safe = rz > 0.001f;
            float inv = __fdividef(1.0f, rz);
            // px = gx*128 + 127.5 ; py = gy*128 + 71.5  (m=256, W=256, H=144)
            float px = safe ? fmaf(rx * inv, 128.0f, 127.5f) : 1.0e8f;
            float py = safe ? fmaf(ry * inv, 128.0f, 71.5f) : 1.0e8f;

            float x0f = floorf(px);
            float y0f = floorf(py);
            float wx = px - x0f;
            float wy = py - y0f;
            int x0 = (int)x0f;
            int y0 = (int)y0f;

            bool vx0 = (unsigned)x0 < (unsigned)IW;
            bool vx1 = (unsigned)(x0 + 1) < (unsigned)IW;
            bool vy0 = (unsigned)y0 < (unsigned)IH;
            bool vy1 = (unsigned)(y0 + 1) < (unsigned)IH;

            // single base address; invalid corners are predicated off (no
            // memory access happens), so no clamping is needed at all.
            int base = y0 * IW + x0;
            float v00 = (vy0 && vx0) ? __ldg(img + base)          : 0.0f;
            float v01 = (vy0 && vx1) ? __ldg(img + base + 1)      : 0.0f;
            float v10 = (vy1 && vx0) ? __ldg(img + base + IW)     : 0.0f;
            float v11 = (vy1 && vx1) ? __ldg(img + base + IW + 1) : 0.0f;

            float top = fmaf(wx, v01 - v00, v00);
            float bot = fmaf(wx, v11 - v10, v10);
            outp[64 * j] = fmaf(wy, bot - top, top);
        }
        rmp += 9;
        img += IH * IW;
        outp += IH * IW;
    }
}

// ---------------------------------------------------------------------------
extern "C" void kernel_launch(void* const* d_in, const int* in_sizes, int n_in,
                              void* d_out, int out_size) {
    const float* stimulus = (const float*)d_in[0];
    const float* persp    = (const float*)d_in[1];
    const float* W1       = (const float*)d_in[2];
    const float* b1       = (const float*)d_in[3];
    const float* W2       = (const float*)d_in[4];
    const float* b2       = (const float*)d_in[5];
    const float* Wp       = (const float*)d_in[6];
    const float* bp       = (const float*)d_in[7];
    float* out = (float*)d_out;

    setup_kernel<<<HR + NB, WR>>>(persp, W1, b1, W2, b2, Wp, bp);
    sample_kernel<<<dim3(HR / 4, NB / BPT), 256>>>(stimulus, out);
}

// round 4
// speedup vs baseline: 1.5005x; 1.1704x over previous
#include <cuda_runtime.h>
#include <math.h>

#define NB 256
#define IH 144
#define IW 256
#define HR 144
#define WR 256
#define F 16
#define D 128
#define BPT 4   // batches per block (sample kernel)

#define FOV_HALF 0.654498469497874f   // 0.5 * 75deg in rad
#define GELU_GAMMA 1.7015043497085571f

// Scratch (no allocations allowed)
__device__ float2 g_dirq[HR * WR];     // homography coords q = d.xy / d.z
__device__ float  g_rm[NB * 9];        // rotation matrices (row 2 pre-scaled by 1/128)

__device__ __forceinline__ float gelu_tanh(float x) {
    // matches jax.nn.gelu(approximate=True)
    float x3 = x * x * x;
    float inner = 0.7978845608028654f * (x + 0.044715f * x3);
    float t = tanhf(inner);
    return 0.5f * x * (1.0f + t);
}

// ---------------------------------------------------------------------------
// Kernel 1 (merged): blocks [0, HR) build the q table; blocks [HR, HR+NB)
// run the per-batch MLP -> Euler angles -> rotation matrix.
// ---------------------------------------------------------------------------
__global__ void setup_kernel(const float* __restrict__ persp,
                             const float* __restrict__ W1, const float* __restrict__ b1,
                             const float* __restrict__ W2, const float* __restrict__ b2,
                             const float* __restrict__ Wp, const float* __restrict__ bp) {
    if (blockIdx.x < HR) {
        // ---- q table: d = (sinc*ax, sinc*ay, cos a); q = d.xy / cos a ----
        int w = threadIdx.x;
        int h = blockIdx.x;
        float gx = ((float)(2 * w + 1 - WR)) * (1.0f / 256.0f);
        float gy = ((float)(2 * h + 1 - HR)) * (1.0f / 256.0f);
        float ax = gx * FOV_HALF;
        float ay = gy * FOV_HALF;
        float a = sqrtf(ax * ax + ay * ay) + 1e-12f;
        float s, c;
        sincosf(a, &s, &c);
        float t = s / (a * c);          // tan(a)/a   (a < 0.75 rad, c > 0.7)
        g_dirq[h * WR + w] = make_float2(t * ax, t * ay);
        return;
    }

    // ---- MLP ----
    __shared__ float sp[F];
    __shared__ float h1[D];
    __shared__ float h2[D];
    __shared__ float sang[3];

    int n = blockIdx.x - HR;
    int tid = threadIdx.x;

    if (tid < F) sp[tid] = persp[n * F + tid];
    __syncthreads();

    if (tid < D) {
        float acc = b1[tid];
#pragma unroll
        for (int k = 0; k < F; k++)
            acc = fmaf(sp[k], __ldg(&W1[k * D + tid]), acc);
        h1[tid] = gelu_tanh(acc) * GELU_GAMMA;
    }
    __syncthreads();

    if (tid < D) {
        float acc2 = b2[tid];
#pragma unroll 8
        for (int k = 0; k < D; k++)
            acc2 = fmaf(h1[k], __ldg(&W2[k * D + tid]), acc2);
        h2[tid] = gelu_tanh(acc2) * GELU_GAMMA;
    }
    __syncthreads();

    if (tid < 3) {
        float a = bp[tid];
        for (int k = 0; k < D; k++)
            a = fmaf(h2[k], __ldg(&Wp[k * 3 + tid]), a);
        sang[tid] = a;
    }
    __syncthreads();

    if (tid == 0) {
        float axr = sang[0], ayr = sang[1], azr = sang[2];
        float cx, sx, cy, sy, cz, sz;
        sincosf(axr, &sx, &cx);
        sincosf(ayr, &sy, &cy);
        sincosf(azr, &sz, &cz);
        // R = Rz @ Ry @ Rx ; row 2 pre-scaled by 1/128 so px = rx/rz128 + 127.5
        float* r = &g_rm[n * 9];
        r[0] = cz * cy;
        r[1] = cz * sy * sx - sz * cx;
        r[2] = cz * sy * cx + sz * sx;
        r[3] = sz * cy;
        r[4] = sz * sy * sx + cz * cx;
        r[5] = sz * sy * cx - cz * sx;
        r[6] = -sy            * 0.0078125f;
        r[7] = cy * sx        * 0.0078125f;
        r[8] = cy * cx        * 0.0078125f;
    }
}

// ---------------------------------------------------------------------------
// Kernel 2: rotate rays (homography form), project, bilinear sample.
//   R2 layout (best occupancy): block = 256 = one retina row, BPT=4 batches,
//   rotation via shared broadcast. grid = (HR, NB/BPT)
// ---------------------------------------------------------------------------
__global__ void __launch_bounds__(256) sample_kernel(const float* __restrict__ stim,
                                                     float* __restrict__ out) {
    __shared__ float r[BPT * 9];
    int w = threadIdx.x;
    int h = blockIdx.x;
    int nb = blockIdx.y * BPT;

    if (threadIdx.x < BPT * 9) r[threadIdx.x] = g_rm[nb * 9 + threadIdx.x];
    __syncthreads();

    float2 q = g_dirq[h * WR + w];

    const float* img = stim + (size_t)nb * (IH * IW);
    float* outp = out + ((size_t)nb * IH + h) * IW + w;

#pragma unroll
    for (int b = 0; b < BPT; b++) {
        const float* rb = &r[b * 9];
        float rx = fmaf(rb[0], q.x, fmaf(rb[1], q.y, rb[2]));
        float ry = fmaf(rb[3], q.x, fmaf(rb[4], q.y, rb[5]));
        float rz = fmaf(rb[6], q.x, fmaf(rb[7], q.y, rb[8]));  // = true rz/128

        bool safe = rz > 7.8125e-6f;                 // 0.001/128
        float inv = __fdividef(1.0f, rz);
        float px = safe ? fmaf(rx, inv, 127.5f) : 1.0e8f;
        float py = safe ? fmaf(ry, inv, 71.5f)  : 1.0e8f;

        float x0f = floorf(px);
        float y0f = floorf(py);
        float wx = px - x0f;
        float wy = py - y0f;
        int x0 = (int)x0f;
        int y0 = (int)y0f;

        bool vx0 = (unsigned)x0 < (unsigned)IW;
        bool vx1 = (unsigned)(x0 + 1) < (unsigned)IW;
        bool vy0 = (unsigned)y0 < (unsigned)IH;
        bool vy1 = (unsigned)(y0 + 1) < (unsigned)IH;

        // single base; invalid corners are predicated off — no clamping.
        int base = y0 * IW + x0;
        float v00 = (vy0 && vx0) ? __ldg(img + base)          : 0.0f;
        float v01 = (vy0 && vx1) ? __ldg(img + base + 1)      : 0.0f;
        float v10 = (vy1 && vx0) ? __ldg(img + base + IW)     : 0.0f;
        float v11 = (vy1 && vx1) ? __ldg(img + base + IW + 1) : 0.0f;

        float top = fmaf(wx, v01 - v00, v00);
        float bot = fmaf(wx, v11 - v10, v10);
        outp[(size_t)b * (IH * IW)] = fmaf(wy, bot - top, top);

        img += IH * IW;
    }
}

// ---------------------------------------------------------------------------
extern "C" void kernel_launch(void* const* d_in, const int* in_sizes, int n_in,
                              void* d_out, int out_size) {
    const float* stimulus = (const float*)d_in[0];
    const float* persp    = (const float*)d_in[1];
    const float* W1       = (const float*)d_in[2];
    const float* b1       = (const float*)d_in[3];
    const float* W2       = (const float*)d_in[4];
    const float* b2       = (const float*)d_in[5];
    const float* Wp       = (const float*)d_in[6];
    const float* bp       = (const float*)d_in[7];
    float* out = (float*)d_out;

    setup_kernel<<<HR + NB, WR>>>(persp, W1, b1, W2, b2, Wp, bp);
    sample_kernel<<<dim3(HR, NB / BPT), 256>>>(stimulus, out);
}